// round 3
// baseline (speedup 1.0000x reference)
#include <cuda_runtime.h>
#include <cstdint>

#define RB 16
#define NC 80
#define NB 16
#define NA 8400
#define CHN 144
#define KP 1024
#define MAXDET 300
#define CONF 0.25f
#define IOUT 0.45f

// ---------------- scratch (no allocations allowed) ----------------
__device__ float4 g_boxes[NB * NA];
__device__ float  g_score[NB * NA];
__device__ int    g_label[NB * NA];
__device__ unsigned long long g_keys[NB * NA];

__device__ __forceinline__ int read_dim(const int* p) {
    if (!p) return 640;
    int v = *p;
    if (v > 0 && v < 100000) return v;
    float f = __int_as_float(v);
    return (int)f;
}

// ---------------- Phase A: decode (DFL + sigmoid/argmax), 2 anchors/thread --------
__global__ __launch_bounds__(128) void decode_k(const float* __restrict__ p0,
                                                const float* __restrict__ p1,
                                                const float* __restrict__ p2,
                                                const int* pH, const int* pW) {
    int gid = blockIdx.x * blockDim.x + threadIdx.x;
    const int tot = NB * NA / 2;
    if (gid >= tot) return;
    int b = gid / (NA / 2);
    int a2 = (gid - b * (NA / 2)) * 2;

    const float* p; int W, stride, lb, HW;
    if (a2 < 6400)      { p = p0; W = 80; stride = 8;  lb = 0;    HW = 6400; }
    else if (a2 < 8000) { p = p1; W = 40; stride = 16; lb = 6400; HW = 1600; }
    else                { p = p2; W = 20; stride = 32; lb = 8000; HW = 400;  }
    int hw = a2 - lb;
    int HW2 = HW >> 1;
    const float2* base = (const float2*)(p + (size_t)b * CHN * HW) + (hw >> 1);

    // DFL: per side, softmax over 16 bins (max-subtracted, identical op order to
    // the validated kernel), expectation * stride.
    float2 dd[4];
    #pragma unroll
    for (int k = 0; k < 4; k++) {
        float2 v[RB];
        #pragma unroll
        for (int r = 0; r < RB; r++) v[r] = base[(size_t)(k * RB + r) * HW2];
        float mxx = -1e30f, mxy = -1e30f;
        #pragma unroll
        for (int r = 0; r < RB; r++) { mxx = fmaxf(mxx, v[r].x); mxy = fmaxf(mxy, v[r].y); }
        float sx = 0.f, wsx = 0.f, sy = 0.f, wsy = 0.f;
        #pragma unroll
        for (int r = 0; r < RB; r++) {
            float fr = (float)r;
            float ex = expf(v[r].x - mxx); sx += ex; wsx += ex * fr;
            float ey = expf(v[r].y - mxy); sy += ey; wsy += ey * fr;
        }
        dd[k].x = wsx / sx * (float)stride;
        dd[k].y = wsy / sy * (float)stride;
    }

    // class max + first-argmax (strict >, first wins)
    float2 mx2 = base[(size_t)64 * HW2];
    int lx = 0, ly = 0;
    #pragma unroll 8
    for (int c = 1; c < NC; c++) {
        float2 z = base[(size_t)(64 + c) * HW2];
        if (z.x > mx2.x) { mx2.x = z.x; lx = c; }
        if (z.y > mx2.y) { mx2.y = z.y; ly = c; }
    }

    int himg = read_dim(pH), wimg = read_dim(pW);
    float hiW = (float)(wimg - 1), hiH = (float)(himg - 1);
    float st = (float)stride;
    int y0 = hw / W, x0 = hw % W;
    float cy = ((float)y0 + 0.5f) * st;

    #pragma unroll
    for (int j = 0; j < 2; j++) {
        float dl = j ? dd[0].y : dd[0].x;
        float dt = j ? dd[1].y : dd[1].x;
        float dr = j ? dd[2].y : dd[2].x;
        float db = j ? dd[3].y : dd[3].x;
        float mxc = j ? mx2.y : mx2.x;
        int   lbl = j ? ly : lx;
        float cx = ((float)(x0 + j) + 0.5f) * st;
        float x1 = fminf(fmaxf(cx - dl, 0.f), hiW);
        float y1 = fminf(fmaxf(cy - dt, 0.f), hiH);
        float x2 = fminf(fmaxf(cx + dr, 0.f), hiW);
        float y2 = fminf(fmaxf(cy + db, 0.f), hiH);
        int g = b * NA + a2 + j;
        g_boxes[g] = make_float4(x1, y1, x2, y2);
        g_label[g] = lbl;
        float sc = 1.0f / (1.0f + expf(-mxc));
        float sp = (sc > CONF) ? sc : -1.0f;
        g_score[g] = sp;
        unsigned u = __float_as_uint(sp);
        u = (u & 0x80000000u) ? ~u : (u | 0x80000000u);
        g_keys[g] = ((unsigned long long)(~u) << 32) | (unsigned)(a2 + j);
    }
}

// ---------------- Phase B: fused radix-select top-1024 + sort + NMS + output -------
__global__ __launch_bounds__(1024) void topk_nms_k(float* __restrict__ out) {
    __shared__ unsigned long long gath[KP];     // 8KB  (gather + sort exchange)
    __shared__ unsigned int hist[2048];         // 8KB
    __shared__ float4 sbox[KP];                 // 16KB
    __shared__ float  ssc[KP];                  // 4KB
    __shared__ short  slab[KP];                 // 2KB
    __shared__ unsigned char skeep[KP];         // 1KB
    __shared__ int wsum[33];
    __shared__ unsigned int wtot[32];
    __shared__ int s_b, s_rank, s_cnt, s_gcnt;

    int b = blockIdx.x, tid = threadIdx.x, w = tid >> 5, lane = tid & 31;
    const unsigned long long* keys = g_keys + (size_t)b * NA;

    // --- exact radix select: find prefix of the 1024th-smallest key (keys unique) ---
    unsigned long long prefix = 0, pmask = 0;
    int rank = KP;
    bool found = false;
    const int shifts[6] = {53, 42, 31, 20, 9, 0};
    #pragma unroll 1
    for (int pass = 0; pass < 6 && !found; pass++) {
        int sh = shifts[pass];
        unsigned bm = (pass == 5) ? 511u : 2047u;
        hist[tid] = 0; hist[tid + 1024] = 0;
        __syncthreads();
        // histogram with warp-aggregated atomics (scores cluster into few buckets)
        #pragma unroll 1
        for (int n = 0; n < 9; n++) {
            int i = tid + n * 1024;
            bool valid = false; unsigned bucket = 0xFFFFFFFFu;
            if (i < NA) {
                unsigned long long k = keys[i];
                if ((k & pmask) == prefix) { valid = true; bucket = (unsigned)(k >> sh) & bm; }
            }
            unsigned grp = __match_any_sync(0xFFFFFFFFu, bucket);
            if (valid && lane == (__ffs(grp) - 1))
                atomicAdd(&hist[bucket], (unsigned)__popc(grp));
        }
        __syncthreads();
        // inclusive scan over 2048 buckets (2 per thread)
        unsigned e0 = hist[2 * tid], e1 = hist[2 * tid + 1];
        unsigned incl = e0 + e1;
        #pragma unroll
        for (int o = 1; o < 32; o <<= 1) {
            unsigned t = __shfl_up_sync(0xFFFFFFFFu, incl, o);
            if (lane >= o) incl += t;
        }
        if (lane == 31) wtot[w] = incl;
        __syncthreads();
        if (w == 0) {
            unsigned v = wtot[lane], iv = v;
            #pragma unroll
            for (int o = 1; o < 32; o <<= 1) {
                unsigned t = __shfl_up_sync(0xFFFFFFFFu, iv, o);
                if (lane >= o) iv += t;
            }
            wtot[lane] = iv - v;
        }
        __syncthreads();
        unsigned incl1 = wtot[w] + incl;
        unsigned incl0 = incl1 - e1;
        unsigned excl0 = incl0 - e0, excl1 = incl1 - e1;
        unsigned r_ = (unsigned)rank;
        if (e0 && excl0 < r_ && r_ <= incl0) { s_b = 2 * tid;     s_rank = (int)(r_ - excl0); s_cnt = (int)e0; }
        if (e1 && excl1 < r_ && r_ <= incl1) { s_b = 2 * tid + 1; s_rank = (int)(r_ - excl1); s_cnt = (int)e1; }
        __syncthreads();
        prefix |= ((unsigned long long)(unsigned)s_b) << sh;
        pmask  |= ((unsigned long long)bm) << sh;
        rank = s_rank;
        if (s_cnt == 1) found = true;   // prefix now uniquely identifies the kth key
        __syncthreads();
    }
    // gather predicate: (k & pmask) < prefix  => k < kth (definitely in top set);
    // (k & pmask) == prefix => unique => k == kth. So (k & pmask) <= prefix is exact.

    // --- gather exactly 1024 keys (warp-aggregated counter) ---
    if (tid == 0) s_gcnt = 0;
    __syncthreads();
    #pragma unroll 1
    for (int n = 0; n < 9; n++) {
        int i = tid + n * 1024;
        unsigned long long k = 0;
        bool valid = false;
        if (i < NA) { k = keys[i]; valid = ((k & pmask) <= prefix); }
        unsigned bal = __ballot_sync(0xFFFFFFFFu, valid);
        int base = 0;
        if (lane == 0 && bal) base = atomicAdd(&s_gcnt, __popc(bal));
        base = __shfl_sync(0xFFFFFFFFu, base, 0);
        if (valid) gath[base + __popc(bal & ((1u << lane) - 1u))] = k;
    }
    __syncthreads();

    // --- bitonic sort ascending, one element per thread; j<=16 via shuffles ---
    unsigned long long v = gath[tid];
    #pragma unroll 1
    for (int kk = 2; kk <= KP; kk <<= 1) {
        bool up = ((tid & kk) == 0);
        #pragma unroll 1
        for (int j = kk >> 1; j > 0; j >>= 1) {
            unsigned long long pv;
            if (j >= 32) {
                __syncthreads();
                gath[tid] = v;
                __syncthreads();
                pv = gath[tid ^ j];
            } else {
                pv = __shfl_xor_sync(0xFFFFFFFFu, v, j);
            }
            bool takeMin = (up == ((tid & j) == 0));
            bool swap = (v > pv) == takeMin ? false : true;
            // keep min if takeMin, else max
            unsigned long long mn = (v < pv) ? v : pv;
            unsigned long long mx = (v < pv) ? pv : v;
            v = takeMin ? mn : mx;
            (void)swap;
        }
    }
    __syncthreads();

    // --- NMS (cross-class IoU exactly 0 due to 4096 class offset -> 80 chains) ---
    unsigned a = (unsigned)(v & 0xFFFFFFFFu);
    int g = b * NA + (int)a;
    sbox[tid] = g_boxes[g];
    ssc[tid]  = g_score[g];
    slab[tid] = (short)g_label[g];
    skeep[tid] = 0;
    __syncthreads();

    for (int c = w; c < NC; c += 32) {
        float4 kept[4];
        int nk = 0;
        float off = (float)c * 4096.0f;
        for (int bk = 0; bk < KP; bk += 32) {
            int k2 = bk + lane;
            bool m = (slab[k2] == c) && (ssc[k2] > CONF);
            unsigned mm = __ballot_sync(0xFFFFFFFFu, m);
            while (mm) {
                int kk2 = bk + (__ffs(mm) - 1); mm &= mm - 1;
                float4 bx = sbox[kk2];
                float x1 = __fadd_rn(bx.x, off), y1 = __fadd_rn(bx.y, off);
                float x2 = __fadd_rn(bx.z, off), y2 = __fadd_rn(bx.w, off);
                float areaC = __fmul_rn(__fsub_rn(x2, x1), __fsub_rn(y2, y1));
                bool sup = false;
                #pragma unroll
                for (int s2 = 0; s2 < 4; s2++) {
                    if (s2 * 32 + lane < nk) {
                        float4 kb = kept[s2];
                        float lx2 = fmaxf(x1, kb.x), ly2 = fmaxf(y1, kb.y);
                        float rx = fminf(x2, kb.z), ry = fminf(y2, kb.w);
                        float iw = fmaxf(__fsub_rn(rx, lx2), 0.f);
                        float ih = fmaxf(__fsub_rn(ry, ly2), 0.f);
                        float inter = __fmul_rn(iw, ih);
                        float areaK = __fmul_rn(__fsub_rn(kb.z, kb.x), __fsub_rn(kb.w, kb.y));
                        float den = __fadd_rn(__fsub_rn(__fadd_rn(areaK, areaC), inter), 1e-7f);
                        if (__fdiv_rn(inter, den) > IOUT) sup = true;
                    }
                }
                if (__ballot_sync(0xFFFFFFFFu, sup) == 0u) {
                    int slot = nk >> 5;
                    if (lane == (nk & 31)) {
                        float4 nb = make_float4(x1, y1, x2, y2);
                        if (slot == 0) kept[0] = nb;
                        else if (slot == 1) kept[1] = nb;
                        else if (slot == 2) kept[2] = nb;
                        else kept[3] = nb;
                    }
                    if (lane == 0) skeep[kk2] = 1;
                    nk++;
                }
            }
        }
    }
    __syncthreads();

    // rank = exclusive prefix of keep flags in score order
    int kv = skeep[tid];
    unsigned bal2 = __ballot_sync(0xFFFFFFFFu, kv != 0);
    int wpre = __popc(bal2 & ((1u << lane) - 1u));
    if (lane == 0) wsum[w] = __popc(bal2);
    __syncthreads();
    if (w == 0) {
        int vv = wsum[lane], orig = vv;
        #pragma unroll
        for (int o = 1; o < 32; o <<= 1) {
            int t = __shfl_up_sync(0xFFFFFFFFu, vv, o);
            if (lane >= o) vv += t;
        }
        wsum[lane] = vv - orig;
        if (lane == 31) wsum[32] = vv;
    }
    __syncthreads();
    int n = min(wsum[32], MAXDET);

    const int OB = 0;
    const int OS = NB * MAXDET * 4;
    const int OL = OS + NB * MAXDET;
    const int OV = OL + NB * MAXDET;

    if (kv) {
        int rk = wsum[w] + wpre;
        if (rk < MAXDET) {
            float4 bx = sbox[tid];
            float* ob = out + OB + ((size_t)b * MAXDET + rk) * 4;
            ob[0] = bx.x; ob[1] = bx.y; ob[2] = bx.z; ob[3] = bx.w;
            out[OS + b * MAXDET + rk] = ssc[tid];
            out[OL + b * MAXDET + rk] = (float)slab[tid];
        }
    }
    if (tid < MAXDET) {
        if (tid >= n) {
            float* ob = out + OB + ((size_t)b * MAXDET + tid) * 4;
            ob[0] = 0.f; ob[1] = 0.f; ob[2] = 0.f; ob[3] = 0.f;
            out[OS + b * MAXDET + tid] = 0.f;
            out[OL + b * MAXDET + tid] = -1.f;
        }
        out[OV + b * MAXDET + tid] = (tid < n) ? 1.f : 0.f;
    }
}

// ---------------- launch ----------------
extern "C" void kernel_launch(void* const* d_in, const int* in_sizes, int n_in,
                              void* d_out, int out_size) {
    (void)in_sizes; (void)out_size;
    const float* p0 = (const float*)d_in[0];
    const float* p1 = (const float*)d_in[1];
    const float* p2 = (const float*)d_in[2];
    const int* pH = (n_in > 3) ? (const int*)d_in[3] : nullptr;
    const int* pW = (n_in > 4) ? (const int*)d_in[4] : nullptr;

    int tot = NB * NA / 2;
    decode_k<<<(tot + 127) / 128, 128>>>(p0, p1, p2, pH, pW);
    topk_nms_k<<<NB, 1024>>>((float*)d_out);
}

// round 5
// speedup vs baseline: 1.1567x; 1.1567x over previous
#include <cuda_runtime.h>
#include <cstdint>

#define RB 16
#define NC 80
#define NB 16
#define NA 8400
#define CHN 144
#define KP 1024
#define MAXDET 300
#define CONF 0.25f
#define IOUT 0.45f

// ---------------- scratch (no allocations allowed) ----------------
__device__ float4 g_boxes[NB * NA];
__device__ float  g_score[NB * NA];
__device__ int    g_label[NB * NA];
__device__ unsigned long long g_keys[NB * NA];

__device__ __forceinline__ int read_dim(const int* p) {
    if (!p) return 640;
    int v = *p;
    if (v > 0 && v < 100000) return v;
    float f = __int_as_float(v);
    return (int)f;
}

__device__ __forceinline__ float f4c(const float4& f, int j) {
    return (j == 0) ? f.x : (j == 1) ? f.y : (j == 2) ? f.z : f.w;
}

// ---------------- Phase A: decode (DFL + sigmoid/argmax), 4 anchors/thread --------
__global__ __launch_bounds__(128) void decode_k(const float* __restrict__ p0,
                                                const float* __restrict__ p1,
                                                const float* __restrict__ p2,
                                                const int* pH, const int* pW) {
    int gid = blockIdx.x * blockDim.x + threadIdx.x;
    const int tot = NB * NA / 4;
    if (gid >= tot) return;
    int b = gid / (NA / 4);
    int a4 = (gid - b * (NA / 4)) * 4;

    const float* p; int W, stride, lb, HW;
    if (a4 < 6400)      { p = p0; W = 80; stride = 8;  lb = 0;    HW = 6400; }
    else if (a4 < 8000) { p = p1; W = 40; stride = 16; lb = 6400; HW = 1600; }
    else                { p = p2; W = 20; stride = 32; lb = 8000; HW = 400;  }
    int hw = a4 - lb;
    int HW4 = HW >> 2;
    const float4* base = (const float4*)(p + (size_t)b * CHN * HW) + (hw >> 2);

    // DFL: per side, softmax over 16 bins (max-subtracted, per-anchor op order
    // identical to the validated kernel), expectation * stride.
    float4 dd[4];
    #pragma unroll
    for (int k = 0; k < 4; k++) {
        float4 v[RB];
        #pragma unroll
        for (int r = 0; r < RB; r++) v[r] = base[(size_t)(k * RB + r) * HW4];
        float4 mx = make_float4(-1e30f, -1e30f, -1e30f, -1e30f);
        #pragma unroll
        for (int r = 0; r < RB; r++) {
            mx.x = fmaxf(mx.x, v[r].x); mx.y = fmaxf(mx.y, v[r].y);
            mx.z = fmaxf(mx.z, v[r].z); mx.w = fmaxf(mx.w, v[r].w);
        }
        float4 s = make_float4(0.f, 0.f, 0.f, 0.f);
        float4 ws = make_float4(0.f, 0.f, 0.f, 0.f);
        #pragma unroll
        for (int r = 0; r < RB; r++) {
            float fr = (float)r;
            float ex = expf(v[r].x - mx.x); s.x += ex; ws.x += ex * fr;
            float ey = expf(v[r].y - mx.y); s.y += ey; ws.y += ey * fr;
            float ez = expf(v[r].z - mx.z); s.z += ez; ws.z += ez * fr;
            float ew = expf(v[r].w - mx.w); s.w += ew; ws.w += ew * fr;
        }
        float st = (float)stride;
        dd[k].x = ws.x / s.x * st; dd[k].y = ws.y / s.y * st;
        dd[k].z = ws.z / s.z * st; dd[k].w = ws.w / s.w * st;
    }

    // class max + first-argmax (strict >, first wins)
    float4 mx2 = base[(size_t)64 * HW4];
    int lab[4] = {0, 0, 0, 0};
    #pragma unroll 8
    for (int c = 1; c < NC; c++) {
        float4 z = base[(size_t)(64 + c) * HW4];
        if (z.x > mx2.x) { mx2.x = z.x; lab[0] = c; }
        if (z.y > mx2.y) { mx2.y = z.y; lab[1] = c; }
        if (z.z > mx2.z) { mx2.z = z.z; lab[2] = c; }
        if (z.w > mx2.w) { mx2.w = z.w; lab[3] = c; }
    }

    int himg = read_dim(pH), wimg = read_dim(pW);
    float hiW = (float)(wimg - 1), hiH = (float)(himg - 1);
    float st = (float)stride;
    int y0 = hw / W, x0 = hw % W;      // hw%4==0 and W%4==0 -> 4 anchors same row
    float cy = ((float)y0 + 0.5f) * st;

    #pragma unroll
    for (int j = 0; j < 4; j++) {
        float dl = f4c(dd[0], j), dt = f4c(dd[1], j);
        float dr = f4c(dd[2], j), db = f4c(dd[3], j);
        float mxc = f4c(mx2, j);
        int   lbl = lab[j];
        float cx = ((float)(x0 + j) + 0.5f) * st;
        float x1 = fminf(fmaxf(cx - dl, 0.f), hiW);
        float y1 = fminf(fmaxf(cy - dt, 0.f), hiH);
        float x2 = fminf(fmaxf(cx + dr, 0.f), hiW);
        float y2 = fminf(fmaxf(cy + db, 0.f), hiH);
        int g = b * NA + a4 + j;
        g_boxes[g] = make_float4(x1, y1, x2, y2);
        g_label[g] = lbl;
        float sc = 1.0f / (1.0f + expf(-mxc));
        float sp = (sc > CONF) ? sc : -1.0f;
        g_score[g] = sp;
        unsigned u = __float_as_uint(sp);
        u = (u & 0x80000000u) ? ~u : (u | 0x80000000u);
        g_keys[g] = ((unsigned long long)(~u) << 32) | (unsigned)(a4 + j);
    }
}

// ---------------- Phase B: fused radix-select top-1024 + sort + NMS + output -------
__global__ __launch_bounds__(1024) void topk_nms_k(float* __restrict__ out) {
    __shared__ unsigned long long gath[KP];     // 8KB
    __shared__ unsigned int hist[2048];         // 8KB
    __shared__ unsigned long long mini[64];     // bucket keys at shortcut
    __shared__ float4 sbox[KP];                 // 16KB
    __shared__ float  ssc[KP];                  // 4KB
    __shared__ short  slab[KP];                 // 2KB
    __shared__ unsigned char skeep[KP];         // 1KB
    __shared__ int wsum[33];
    __shared__ unsigned int wtot[32];
    __shared__ int s_b, s_rank, s_cnt, s_gcnt, s_mcnt;

    int b = blockIdx.x, tid = threadIdx.x, w = tid >> 5, lane = tid & 31;
    const unsigned long long* keys = g_keys + (size_t)b * NA;

    // --- radix select: stop as soon as the rank bucket has <= 64 keys ---
    unsigned long long prefix = 0, pmask = 0;
    int rank = KP;
    const int shifts[6] = {53, 42, 31, 20, 9, 0};
    #pragma unroll 1
    for (int pass = 0; pass < 6; pass++) {
        int sh = shifts[pass];
        unsigned bm = (pass == 5) ? 511u : 2047u;
        hist[tid] = 0; hist[tid + 1024] = 0;
        __syncthreads();
        for (int i = tid; i < NA; i += 1024) {     // no warp collectives inside: safe
            unsigned long long k = keys[i];
            if ((k & pmask) == prefix)
                atomicAdd(&hist[(unsigned)(k >> sh) & bm], 1u);
        }
        __syncthreads();
        // inclusive scan over 2048 buckets (2 per thread)
        unsigned e0 = hist[2 * tid], e1 = hist[2 * tid + 1];
        unsigned incl = e0 + e1;
        #pragma unroll
        for (int o = 1; o < 32; o <<= 1) {
            unsigned t = __shfl_up_sync(0xFFFFFFFFu, incl, o);
            if (lane >= o) incl += t;
        }
        if (lane == 31) wtot[w] = incl;
        __syncthreads();
        if (w == 0) {
            unsigned v = wtot[lane], iv = v;
            #pragma unroll
            for (int o = 1; o < 32; o <<= 1) {
                unsigned t = __shfl_up_sync(0xFFFFFFFFu, iv, o);
                if (lane >= o) iv += t;
            }
            wtot[lane] = iv - v;
        }
        __syncthreads();
        unsigned incl1 = wtot[w] + incl;
        unsigned incl0 = incl1 - e1;
        unsigned excl0 = incl0 - e0, excl1 = incl1 - e1;
        unsigned r_ = (unsigned)rank;
        if (e0 && excl0 < r_ && r_ <= incl0) { s_b = 2 * tid;     s_rank = (int)(r_ - excl0); s_cnt = (int)e0; }
        if (e1 && excl1 < r_ && r_ <= incl1) { s_b = 2 * tid + 1; s_rank = (int)(r_ - excl1); s_cnt = (int)e1; }
        __syncthreads();
        prefix |= ((unsigned long long)(unsigned)s_b) << sh;
        pmask  |= ((unsigned long long)bm) << sh;
        rank = s_rank;
        if (s_cnt <= 64) break;   // uniform decision (smem read after barrier)
    }
    int bcnt = s_cnt, brank = rank;          // rank of kth within bucket (1-based)
    int below = KP - brank;                  // keys strictly below the bucket

    // --- single combined gather sweep (UNIFORM trip count for ballot safety):
    //     below-keys -> gath[0..below), bucket-keys (<=64) -> mini[] ---
    if (tid == 0) { s_gcnt = 0; s_mcnt = 0; }
    __syncthreads();
    #pragma unroll 1
    for (int n = 0; n < 9; n++) {                 // 9*1024 >= NA, same count all threads
        int i = tid + n * 1024;
        unsigned long long k = 0, masked = ~0ull;
        if (i < NA) { k = keys[i]; masked = k & pmask; }
        bool vlo = (masked < prefix);
        bool vm  = (masked == prefix) && (i < NA);
        unsigned blo = __ballot_sync(0xFFFFFFFFu, vlo);
        unsigned bmk = __ballot_sync(0xFFFFFFFFu, vm);
        int base = 0, base2 = 0;
        if (lane == 0) {
            if (blo) base  = atomicAdd(&s_gcnt, __popc(blo));
            if (bmk) base2 = atomicAdd(&s_mcnt, __popc(bmk));
        }
        base  = __shfl_sync(0xFFFFFFFFu, base, 0);
        base2 = __shfl_sync(0xFFFFFFFFu, base2, 0);
        if (vlo) gath[base  + __popc(blo & ((1u << lane) - 1u))] = k;
        if (vm)  mini[base2 + __popc(bmk & ((1u << lane) - 1u))] = k;
    }
    __syncthreads();
    // rank bucket keys exactly; the brank smallest join the top-1024
    if (tid < bcnt) {
        unsigned long long m = mini[tid];
        int r = 0;
        for (int j = 0; j < bcnt; j++) r += (mini[j] < m);   // keys unique
        if (r < brank) gath[below + r] = m;
    }
    __syncthreads();

    // --- bitonic sort ascending (validated round-2 form) ---
    for (int kk = 2; kk <= KP; kk <<= 1)
        for (int j = kk >> 1; j > 0; j >>= 1) {
            int i = tid, ixj = i ^ j;
            if (ixj > i && i < KP) {
                bool asc = ((i & kk) == 0);
                unsigned long long av = gath[i], bv = gath[ixj];
                if ((av > bv) == asc) { gath[i] = bv; gath[ixj] = av; }
            }
            __syncthreads();
        }

    // --- NMS (cross-class IoU exactly 0 due to 4096 class offset -> 80 chains) ---
    unsigned long long key = gath[tid];
    unsigned a = (unsigned)(key & 0xFFFFFFFFu);
    int g = b * NA + (int)a;
    sbox[tid] = g_boxes[g];
    ssc[tid]  = g_score[g];
    slab[tid] = (short)g_label[g];
    skeep[tid] = 0;
    __syncthreads();

    for (int c = w; c < NC; c += 32) {
        float4 kept[4];
        int nk = 0;
        float off = (float)c * 4096.0f;
        for (int bk = 0; bk < KP; bk += 32) {
            int k2 = bk + lane;
            bool m = (slab[k2] == c) && (ssc[k2] > CONF);
            unsigned mm = __ballot_sync(0xFFFFFFFFu, m);
            while (mm) {
                int kk2 = bk + (__ffs(mm) - 1); mm &= mm - 1;
                float4 bx = sbox[kk2];
                float x1 = __fadd_rn(bx.x, off), y1 = __fadd_rn(bx.y, off);
                float x2 = __fadd_rn(bx.z, off), y2 = __fadd_rn(bx.w, off);
                float areaC = __fmul_rn(__fsub_rn(x2, x1), __fsub_rn(y2, y1));
                bool sup = false;
                #pragma unroll
                for (int s2 = 0; s2 < 4; s2++) {
                    if (s2 * 32 + lane < nk) {
                        float4 kb = kept[s2];
                        float lx2 = fmaxf(x1, kb.x), ly2 = fmaxf(y1, kb.y);
                        float rx = fminf(x2, kb.z), ry = fminf(y2, kb.w);
                        float iw = fmaxf(__fsub_rn(rx, lx2), 0.f);
                        float ih = fmaxf(__fsub_rn(ry, ly2), 0.f);
                        float inter = __fmul_rn(iw, ih);
                        float areaK = __fmul_rn(__fsub_rn(kb.z, kb.x), __fsub_rn(kb.w, kb.y));
                        float den = __fadd_rn(__fsub_rn(__fadd_rn(areaK, areaC), inter), 1e-7f);
                        if (__fdiv_rn(inter, den) > IOUT) sup = true;
                    }
                }
                if (__ballot_sync(0xFFFFFFFFu, sup) == 0u) {
                    int slot = nk >> 5;
                    if (lane == (nk & 31)) {
                        float4 nb = make_float4(x1, y1, x2, y2);
                        if (slot == 0) kept[0] = nb;
                        else if (slot == 1) kept[1] = nb;
                        else if (slot == 2) kept[2] = nb;
                        else kept[3] = nb;
                    }
                    if (lane == 0) skeep[kk2] = 1;
                    nk++;
                }
            }
        }
    }
    __syncthreads();

    // rank = exclusive prefix of keep flags in score order
    int kv = skeep[tid];
    unsigned bal2 = __ballot_sync(0xFFFFFFFFu, kv != 0);
    int wpre = __popc(bal2 & ((1u << lane) - 1u));
    if (lane == 0) wsum[w] = __popc(bal2);
    __syncthreads();
    if (w == 0) {
        int vv = wsum[lane], orig = vv;
        #pragma unroll
        for (int o = 1; o < 32; o <<= 1) {
            int t = __shfl_up_sync(0xFFFFFFFFu, vv, o);
            if (lane >= o) vv += t;
        }
        wsum[lane] = vv - orig;
        if (lane == 31) wsum[32] = vv;
    }
    __syncthreads();
    int n = min(wsum[32], MAXDET);

    const int OB = 0;
    const int OS = NB * MAXDET * 4;
    const int OL = OS + NB * MAXDET;
    const int OV = OL + NB * MAXDET;

    if (kv) {
        int rk = wsum[w] + wpre;
        if (rk < MAXDET) {
            float4 bx = sbox[tid];
            float* ob = out + OB + ((size_t)b * MAXDET + rk) * 4;
            ob[0] = bx.x; ob[1] = bx.y; ob[2] = bx.z; ob[3] = bx.w;
            out[OS + b * MAXDET + rk] = ssc[tid];
            out[OL + b * MAXDET + rk] = (float)slab[tid];
        }
    }
    if (tid < MAXDET) {
        if (tid >= n) {
            float* ob = out + OB + ((size_t)b * MAXDET + tid) * 4;
            ob[0] = 0.f; ob[1] = 0.f; ob[2] = 0.f; ob[3] = 0.f;
            out[OS + b * MAXDET + tid] = 0.f;
            out[OL + b * MAXDET + tid] = -1.f;
        }
        out[OV + b * MAXDET + tid] = (tid < n) ? 1.f : 0.f;
    }
}

// ---------------- launch ----------------
extern "C" void kernel_launch(void* const* d_in, const int* in_sizes, int n_in,
                              void* d_out, int out_size) {
    (void)in_sizes; (void)out_size;
    const float* p0 = (const float*)d_in[0];
    const float* p1 = (const float*)d_in[1];
    const float* p2 = (const float*)d_in[2];
    const int* pH = (n_in > 3) ? (const int*)d_in[3] : nullptr;
    const int* pW = (n_in > 4) ? (const int*)d_in[4] : nullptr;

    int tot = NB * NA / 4;
    decode_k<<<(tot + 127) / 128, 128>>>(p0, p1, p2, pH, pW);
    topk_nms_k<<<NB, 1024>>>((float*)d_out);
}